// round 7
// baseline (speedup 1.0000x reference)
#include <cuda_runtime.h>
#include <cuda_bf16.h>

#define BB   32
#define NN   16384
#define DD   64
#define KK   64
#define CPB  8
#define NCTA (BB*CPB)                 // 256
#define NT   512
#define NW   16
#define PTS  2048                     // points per CTA
#define PPT  4                        // points per thread (contiguous)

// ---------------- device globals (static scratch only) --------------------
__device__ unsigned long long g_slot[BB * KK];   // per (batch, round) packed argmax
__device__ unsigned int g_count = 0;             // barrier arrival counter
__device__ unsigned int g_gen   = 0;             // barrier generation (monotonic across replays)

// R1's PROVEN grid-wide barrier, verbatim. All 256 CTAs co-resident
// (occupancy 2 * 148 SMs >= 256), so no deadlock.
__device__ __forceinline__ void grid_sync() {
    __syncthreads();
    if (threadIdx.x == 0) {
        __threadfence();
        unsigned int gen = *(volatile unsigned int*)&g_gen;
        unsigned int prev = atomicAdd(&g_count, 1u);
        if (prev == NCTA - 1) {
            g_count = 0;
            __threadfence();
            *(volatile unsigned int*)&g_gen = gen + 1;
        } else {
            while (*(volatile unsigned int*)&g_gen == gen) { __nanosleep(64); }
        }
        __threadfence();
    }
    __syncthreads();
}

// 32-byte read-only load with L2 evict_last (sm_103 accepts it only on the
// 256-bit form). volatile: keep the loads inside the k-loop (no hoist/spill).
__device__ __forceinline__ void ld_el8(const float* p, float4& v0, float4& v1) {
    unsigned long long a, b, c, d;
    asm volatile("ld.global.nc.L2::evict_last.v4.b64 {%0,%1,%2,%3}, [%4];"
        : "=l"(a), "=l"(b), "=l"(c), "=l"(d) : "l"(p));
    v0.x = __uint_as_float((unsigned)(a));
    v0.y = __uint_as_float((unsigned)(a >> 32));
    v0.z = __uint_as_float((unsigned)(b));
    v0.w = __uint_as_float((unsigned)(b >> 32));
    v1.x = __uint_as_float((unsigned)(c));
    v1.y = __uint_as_float((unsigned)(c >> 32));
    v1.z = __uint_as_float((unsigned)(d));
    v1.w = __uint_as_float((unsigned)(d >> 32));
}

// Squared euclidean distance with R1's EXACT rounding order (the order that
// scored rel_err 0.0): four sequential 16-dim fmaf chains over dim groups,
// combined ((s0+s1)+s2)+s3. Bit-identical to the accepted kernel.
__device__ __forceinline__ float dist_r1(const float* __restrict__ px,
                                         const float* __restrict__ cen) {
    float s[4];
    #pragma unroll
    for (int g = 0; g < 4; ++g) {
        float acc = 0.f;
        #pragma unroll
        for (int h = 0; h < 2; ++h) {           // 8 dims per ld_el8
            float4 v0, v1;
            const int base = g * 16 + h * 8;
            ld_el8(px + base, v0, v1);
            float d;
            d = v0.x - cen[base + 0]; acc = fmaf(d, d, acc);
            d = v0.y - cen[base + 1]; acc = fmaf(d, d, acc);
            d = v0.z - cen[base + 2]; acc = fmaf(d, d, acc);
            d = v0.w - cen[base + 3]; acc = fmaf(d, d, acc);
            d = v1.x - cen[base + 4]; acc = fmaf(d, d, acc);
            d = v1.y - cen[base + 5]; acc = fmaf(d, d, acc);
            d = v1.z - cen[base + 6]; acc = fmaf(d, d, acc);
            d = v1.w - cen[base + 7]; acc = fmaf(d, d, acc);
        }
        s[g] = acc;
    }
    return ((s[0] + s[1]) + s[2]) + s[3];
}

__device__ __forceinline__ unsigned long long warp_max_u64(unsigned long long v) {
    #pragma unroll
    for (int o = 16; o; o >>= 1) {
        unsigned long long u = __shfl_xor_sync(0xffffffffu, v, o);
        v = (v > u) ? v : u;
    }
    return v;
}

__global__ void __launch_bounds__(NT, 2)
kmpp_kernel(const float* __restrict__ data,
            const int*   __restrict__ first_idx,
            float*       __restrict__ out)
{
    __shared__ float s_cen[DD];                   // current (newest) center
    __shared__ unsigned long long s_red[NW];
    __shared__ int s_widx;

    const int t     = threadIdx.x;
    const int lane  = t & 31;
    const int wid   = t >> 5;
    const int cta   = blockIdx.x;
    const int batch = cta / CPB;
    const int chunk = cta % CPB;
    const int pbase = chunk * PTS;
    const float* bd = data + (size_t)batch * NN * DD;
    float* bout     = out  + (size_t)batch * KK * DD;
    const bool leader = (chunk == 0);

    // reset this run's argmax slots (8 per CTA covers BB*KK = 2048)
    if (t < KK * BB / NCTA)
        g_slot[cta * (KK * BB / NCTA) + t] = 0ULL;

    // center 0
    if (t < DD) {
        int i0 = first_idx[batch];
        float c = bd[(size_t)i0 * DD + t];
        s_cen[t] = c;
        if (leader) bout[t] = c;
    }

    // min_d in registers: 4 contiguous points per thread
    float md0 = 3.4e38f, md1 = 3.4e38f, md2 = 3.4e38f, md3 = 3.4e38f;
    const unsigned gidx = (unsigned)(pbase + t * PPT);
    const float* px = bd + (size_t)(pbase + t * PPT) * DD;

    grid_sync();   // slot resets + s_cen visible everywhere

    for (int k = 1; k < KK; ++k) {
        // ---- fused: update min_d vs center (k-1) + local packed argmax ----
        {
            float s0 = dist_r1(px,          s_cen);
            float s1 = dist_r1(px + DD,     s_cen);
            float s2 = dist_r1(px + 2 * DD, s_cen);
            float s3 = dist_r1(px + 3 * DD, s_cen);
            md0 = fminf(md0, s0);
            md1 = fminf(md1, s1);
            md2 = fminf(md2, s2);
            md3 = fminf(md3, s3);
        }
        unsigned long long best;
        {
            unsigned long long p0 = ((unsigned long long)__float_as_uint(md0) << 32) | (unsigned)~(gidx + 0);
            unsigned long long p1 = ((unsigned long long)__float_as_uint(md1) << 32) | (unsigned)~(gidx + 1);
            unsigned long long p2 = ((unsigned long long)__float_as_uint(md2) << 32) | (unsigned)~(gidx + 2);
            unsigned long long p3 = ((unsigned long long)__float_as_uint(md3) << 32) | (unsigned)~(gidx + 3);
            best = p0 > p1 ? p0 : p1;
            best = best > p2 ? best : p2;
            best = best > p3 ? best : p3;
        }
        best = warp_max_u64(best);
        if (lane == 0) s_red[wid] = best;
        __syncthreads();
        if (t == 0) {
            unsigned long long b = s_red[0];
            #pragma unroll
            for (int i = 1; i < NW; ++i) b = (b > s_red[i]) ? b : s_red[i];
            atomicMax(&g_slot[batch * KK + k], b);
        }

        grid_sync();   // all CTAs' maxima for round k deposited

        if (t == 0) {
            unsigned long long v = atomicAdd(&g_slot[batch * KK + k], 0ULL);
            s_widx = (int)(~(unsigned)v);
        }
        __syncthreads();

        // gather winner as the new center (its own min_d auto-zeroes next
        // round since dist_r1(x, x) == +0 bit-exactly)
        int w = s_widx;
        if (t < DD) {
            float c = bd[(size_t)w * DD + t];
            s_cen[t] = c;
            if (leader) bout[k * DD + t] = c;
        }
        __syncthreads();
    }
}

extern "C" void kernel_launch(void* const* d_in, const int* in_sizes, int n_in,
                              void* d_out, int out_size) {
    const float* data      = (const float*)d_in[0];   // (B, N, D) fp32
    const int*   first_idx = (const int*)d_in[1];     // (B,) int32
    float*       out       = (float*)d_out;           // (B, K, D) fp32
    (void)in_sizes; (void)n_in; (void)out_size;
    kmpp_kernel<<<NCTA, NT>>>(data, first_idx, out);
}